// round 1
// baseline (speedup 1.0000x reference)
#include <cuda_runtime.h>

// Problem constants
#define AA 32
#define RR 992          // AA*(AA-1)
#define BB 4
#define TFULL 64
#define TT 63           // only t < T-1 contributes to output
#define DD 64
#define SSZ 4
#define MH 256
#define MO 256
#define NH 256
#define ROWS (BB*TT*AA) // 8064 (b,t,a) rows
#define BT (BB*TT)      // 252

// Scratch (device globals; allocation-free)
__device__ float g_P[6 * ROWS * MH];   // fc1 partials: [type'*2+half][row][n]
__device__ float g_XO1[ROWS * NH];     // x @ out_fc1_w[:64,:]
__device__ float g_G[BB * TT * RR * 3];
__device__ float g_AGG[ROWS * MO];

__device__ __forceinline__ float lrelu(float v) { return v > 0.f ? v : 0.01f * v; }

// ---------------------------------------------------------------------------
// Kernel 1: per-agent fc1 partials + x-half of out_fc1.
// GEMM: x (A=32 rows, K=64) x 1792 columns, one CTA per (b,t).
// ---------------------------------------------------------------------------
__global__ __launch_bounds__(256) void k_fc1(const float* __restrict__ inputs,
                                             const float* __restrict__ w1,
                                             const float* __restrict__ wo1) {
    __shared__ __align__(16) float xsT[64 * 36];   // [d][a] padded
    int bt = blockIdx.x;
    int b = bt / TT;
    int t = bt - b * TT;
    int tid = threadIdx.x;

    for (int idx = tid; idx < AA * DD; idx += 256) {
        int a = idx >> 6, d = idx & 63;
        xsT[d * 36 + a] = inputs[((b * AA + a) * TFULL + t) * DD + d];
    }
    __syncthreads();

    #pragma unroll 1
    for (int j = 0; j < 7; j++) {
        int c = tid + (j << 8);          // 0..1791
        int n = c & 255;
        const float* wcol;
        if (c < 1536) {
            int ip = c >> 9;             // type' 0..2  (actual type ip+1)
            int half = (c >> 8) & 1;     // 0 = send, 1 = rec
            wcol = w1 + ((ip + 1) * 128 + half * 64) * 256 + n;
        } else {
            wcol = wo1 + n;              // out_fc1_w rows 0..63 (x part)
        }
        float acc[32];
        #pragma unroll
        for (int a2 = 0; a2 < 32; a2++) acc[a2] = 0.f;

        #pragma unroll 4
        for (int d = 0; d < 64; d++) {
            float w = wcol[d * 256];
            const float4* row = (const float4*)(xsT + d * 36);
            #pragma unroll
            for (int h = 0; h < 8; h++) {
                float4 q = row[h];
                acc[4 * h + 0] += q.x * w;
                acc[4 * h + 1] += q.y * w;
                acc[4 * h + 2] += q.z * w;
                acc[4 * h + 3] += q.w * w;
            }
        }
        float* dst = (c < 1536) ? (g_P + (size_t)(c >> 8) * (ROWS * MH)) : g_XO1;
        #pragma unroll
        for (int a2 = 0; a2 < 32; a2++)
            dst[(size_t)(bt * 32 + a2) * 256 + n] = acc[a2];
    }
}

// ---------------------------------------------------------------------------
// Kernel 2: edge gates g[b,t,r,i] = sum_s rel_type[b,r,s,i] * state[b,send,t,s]
// ---------------------------------------------------------------------------
__global__ __launch_bounds__(256) void k_gate(const float* __restrict__ state,
                                              const float* __restrict__ rel_type) {
    int idx = blockIdx.x * 256 + threadIdx.x;
    if (idx >= BB * TT * RR) return;
    int r = idx % RR;
    int bt = idx / RR;
    int t = bt % TT;
    int b = bt / TT;
    int rec = r / 31;
    int e = r - rec * 31;
    int send = e + (e >= rec);
    const float* stp = state + ((b * AA + send) * TFULL + t) * SSZ;
    const float* rt = rel_type + (size_t)(b * RR + r) * SSZ * 4;
    float s0 = stp[0], s1 = stp[1], s2 = stp[2], s3 = stp[3];
    #pragma unroll
    for (int ip = 0; ip < 3; ip++) {
        float g = rt[0 * 4 + ip + 1] * s0 + rt[1 * 4 + ip + 1] * s1 +
                  rt[2 * 4 + ip + 1] * s2 + rt[3 * 4 + ip + 1] * s3;
        g_G[(size_t)idx * 3 + ip] = g;
    }
}

// ---------------------------------------------------------------------------
// Kernel 3 (heavy): per-(b,t,receiver) message fc2 + gated aggregation.
// One CTA per (b,t,a): 31 edges, 3 types.  fc2 = (31x256) @ (256x256).
// m1 stored transposed+padded in SMEM: per k -> 1 LDG + 8 LDS.128 + 31 FFMA.
// ---------------------------------------------------------------------------
__global__ __launch_bounds__(256) void k_msg(const float* __restrict__ w2,
                                             const float* __restrict__ b1,
                                             const float* __restrict__ b2) {
    __shared__ __align__(16) float sm1[256 * 36];   // [k][e] padded to 36
    __shared__ float gs[31 * 3];                    // [e][type']
    int blk = blockIdx.x;                           // bt*32 + a
    int a = blk & 31;
    int bt = blk >> 5;
    int tid = threadIdx.x;

    if (tid < 93) {
        int e = tid / 3;
        int ip = tid - e * 3;
        gs[tid] = g_G[(size_t)(bt * RR + a * 31 + e) * 3 + ip];
    }

    float agg = 0.f;
    for (int ip = 0; ip < 3; ip++) {
        __syncthreads();   // gs ready (ip=0) / sm1 free for reuse (ip>0)
        {
            const float* Psend = g_P + (size_t)(ip * 2) * (ROWS * MH) + (size_t)(bt * 32) * 256 + tid;
            const float* Prec  = g_P + (size_t)(ip * 2 + 1) * (ROWS * MH) + (size_t)(bt * 32 + a) * 256 + tid;
            float pr = *Prec + b1[(ip + 1) * 256 + tid];
            #pragma unroll
            for (int e = 0; e < 31; e++) {
                int send = e + (e >= a);
                sm1[tid * 36 + e] = lrelu(Psend[send * 256] + pr);
            }
        }
        __syncthreads();

        float acc[31];
        #pragma unroll
        for (int e = 0; e < 31; e++) acc[e] = 0.f;

        const float* wc = w2 + (size_t)(ip + 1) * 65536 + tid;
        #pragma unroll 2
        for (int k = 0; k < 256; k++) {
            float w = wc[k * 256];
            const float4* row = (const float4*)(sm1 + k * 36);
            float vals[32];
            #pragma unroll
            for (int h = 0; h < 8; h++) {
                float4 q = row[h];
                vals[4 * h + 0] = q.x;
                vals[4 * h + 1] = q.y;
                vals[4 * h + 2] = q.z;
                vals[4 * h + 3] = q.w;
            }
            #pragma unroll
            for (int e = 0; e < 31; e++) acc[e] += vals[e] * w;
        }
        float b2n = b2[(ip + 1) * 256 + tid];
        #pragma unroll
        for (int e = 0; e < 31; e++)
            agg += lrelu(acc[e] + b2n) * gs[e * 3 + ip];
    }
    g_AGG[(size_t)blk * 256 + tid] = agg;
}

// ---------------------------------------------------------------------------
// Kernel 4: output MLP, one CTA per (b,t) handling all 32 agents.
// h1 = lrelu(xo1 + agg@Wo1[64:] + b1); h2 = lrelu(h1@Wo2 + b2);
// pred = h2@Wo3 + b3; out = x + pred (t < 63 only), transposed layout.
// ---------------------------------------------------------------------------
__global__ __launch_bounds__(256) void k_out(const float* __restrict__ inputs,
                                             const float* __restrict__ wo1,
                                             const float* __restrict__ bo1,
                                             const float* __restrict__ wo2,
                                             const float* __restrict__ bo2,
                                             const float* __restrict__ wo3,
                                             const float* __restrict__ bo3,
                                             float* __restrict__ out) {
    extern __shared__ float s3[];
    float* sA = s3;              // [256][36]
    float* sB = s3 + 256 * 36;   // [256][36]
    int bt = blockIdx.x;
    int b = bt / TT;
    int t = bt - b * TT;
    int tid = threadIdx.x;

    // load agg transposed: sA[k][a]
    for (int idx = tid; idx < 32 * 256; idx += 256) {
        int a = idx >> 8;
        int k = idx & 255;
        sA[k * 36 + a] = g_AGG[(size_t)(bt * 32 + a) * 256 + k];
    }
    __syncthreads();

    float acc[32];

    // ---- h1 ----
    {
        const float* xb = g_XO1 + (size_t)(bt * 32) * 256 + tid;
        float bb = bo1[tid];
        #pragma unroll
        for (int a2 = 0; a2 < 32; a2++) acc[a2] = xb[a2 * 256] + bb;
        const float* wc = wo1 + 64 * 256 + tid;
        #pragma unroll 2
        for (int k = 0; k < 256; k++) {
            float w = wc[k * 256];
            const float4* row = (const float4*)(sA + k * 36);
            #pragma unroll
            for (int h = 0; h < 8; h++) {
                float4 q = row[h];
                acc[4 * h + 0] += q.x * w;
                acc[4 * h + 1] += q.y * w;
                acc[4 * h + 2] += q.z * w;
                acc[4 * h + 3] += q.w * w;
            }
        }
        #pragma unroll
        for (int a2 = 0; a2 < 32; a2++) sB[tid * 36 + a2] = lrelu(acc[a2]);
    }
    __syncthreads();

    // ---- h2 ----
    {
        float bb = bo2[tid];
        #pragma unroll
        for (int a2 = 0; a2 < 32; a2++) acc[a2] = bb;
        const float* wc = wo2 + tid;
        #pragma unroll 2
        for (int k = 0; k < 256; k++) {
            float w = wc[k * 256];
            const float4* row = (const float4*)(sB + k * 36);
            #pragma unroll
            for (int h = 0; h < 8; h++) {
                float4 q = row[h];
                acc[4 * h + 0] += q.x * w;
                acc[4 * h + 1] += q.y * w;
                acc[4 * h + 2] += q.z * w;
                acc[4 * h + 3] += q.w * w;
            }
        }
        #pragma unroll
        for (int a2 = 0; a2 < 32; a2++) acc[a2] = lrelu(acc[a2]);
    }
    __syncthreads();              // all reads of sA done
    #pragma unroll
    for (int a2 = 0; a2 < 32; a2++) sA[tid * 36 + a2] = acc[a2];
    __syncthreads();

    // ---- fc3 partials: thread (kq, d) handles 64 k's for column d ----
    {
        int d = tid & 63;
        int kq = tid >> 6;
        #pragma unroll
        for (int a2 = 0; a2 < 32; a2++) acc[a2] = 0.f;
        const float* wc = wo3 + d;
        int k0 = kq * 64;
        #pragma unroll 2
        for (int k = k0; k < k0 + 64; k++) {
            float w = wc[k * 64];
            const float4* row = (const float4*)(sA + k * 36);
            #pragma unroll
            for (int h = 0; h < 8; h++) {
                float4 q = row[h];
                acc[4 * h + 0] += q.x * w;
                acc[4 * h + 1] += q.y * w;
                acc[4 * h + 2] += q.z * w;
                acc[4 * h + 3] += q.w * w;
            }
        }
        #pragma unroll
        for (int a2 = 0; a2 < 32; a2++) sB[tid * 36 + a2] = acc[a2];
    }
    __syncthreads();

    // ---- reduce partials, add bias + residual, write transposed output ----
    for (int idx = tid; idx < 2048; idx += 256) {
        int a = idx >> 6;
        int d = idx & 63;
        float v = sB[d * 36 + a] + sB[(64 + d) * 36 + a] +
                  sB[(128 + d) * 36 + a] + sB[(192 + d) * 36 + a];
        v += bo3[d];
        v += inputs[((b * AA + a) * TFULL + t) * DD + d];
        out[((size_t)(b * AA + a) * TT + t) * DD + d] = v;
    }
}

// ---------------------------------------------------------------------------
extern "C" void kernel_launch(void* const* d_in, const int* in_sizes, int n_in,
                              void* d_out, int out_size) {
    const float* inputs    = (const float*)d_in[0];
    const float* state     = (const float*)d_in[1];
    const float* rel_type  = (const float*)d_in[2];
    // d_in[3] rel_rec, d_in[4] rel_send: implied by edge ordering, unused
    const float* msg_fc1_w = (const float*)d_in[5];
    const float* msg_fc1_b = (const float*)d_in[6];
    const float* msg_fc2_w = (const float*)d_in[7];
    const float* msg_fc2_b = (const float*)d_in[8];
    const float* out_fc1_w = (const float*)d_in[9];
    const float* out_fc1_b = (const float*)d_in[10];
    const float* out_fc2_w = (const float*)d_in[11];
    const float* out_fc2_b = (const float*)d_in[12];
    const float* out_fc3_w = (const float*)d_in[13];
    const float* out_fc3_b = (const float*)d_in[14];
    float* out = (float*)d_out;

    static_assert(BB * TT * RR == 249984, "edge count");
    cudaFuncSetAttribute(k_out, cudaFuncAttributeMaxDynamicSharedMemorySize, 2 * 256 * 36 * 4);

    k_fc1<<<BT, 256>>>(inputs, msg_fc1_w, out_fc1_w);
    k_gate<<<(BB * TT * RR + 255) / 256, 256>>>(state, rel_type);
    k_msg<<<ROWS, 256>>>(msg_fc2_w, msg_fc1_b, msg_fc2_b);
    k_out<<<BT, 256, 2 * 256 * 36 * 4>>>(inputs, out_fc1_w, out_fc1_b,
                                         out_fc2_w, out_fc2_b,
                                         out_fc3_w, out_fc3_b, out);
}

// round 3
// speedup vs baseline: 1.0739x; 1.0739x over previous
#include <cuda_runtime.h>
#include <cstdint>

// Problem constants
#define AA 32
#define RR 992          // AA*(AA-1)
#define BB 4
#define TFULL 64
#define TT 63           // only t < T-1 contributes to output
#define DD 64
#define SSZ 4
#define MH 256
#define MO 256
#define NH 256
#define ROWS (BB*TT*AA) // 8064 (b,t,a) rows
#define BT (BB*TT)      // 252

// Scratch (device globals; allocation-free)
__device__ float g_P[6 * ROWS * MH];   // fc1 partials: [type'*2+half][row][n]
__device__ float g_XO1[ROWS * NH];     // x @ out_fc1_w[:64,:]
__device__ float g_G[BB * TT * RR * 3];
__device__ float g_AGG[ROWS * MO];

__device__ __forceinline__ float lrelu(float v) { return v > 0.f ? v : 0.01f * v; }

// ---- packed f32x2 helpers (FFMA2 path, sm_103a) ----
__device__ __forceinline__ uint64_t pack_dup(float w) {
    uint64_t r; asm("mov.b64 %0, {%1, %1};" : "=l"(r) : "f"(w)); return r;
}
__device__ __forceinline__ uint64_t pack2(float lo, float hi) {
    uint64_t r; asm("mov.b64 %0, {%1, %2};" : "=l"(r) : "f"(lo), "f"(hi)); return r;
}
__device__ __forceinline__ void ffma2(uint64_t& d, uint64_t a, uint64_t b) {
    asm("fma.rn.f32x2 %0, %1, %2, %0;" : "+l"(d) : "l"(a), "l"(b));
}
__device__ __forceinline__ float lo32(uint64_t v) { return __uint_as_float((uint32_t)v); }
__device__ __forceinline__ float hi32(uint64_t v) { return __uint_as_float((uint32_t)(v >> 32)); }

// ---------------------------------------------------------------------------
// Kernel 1: per-agent fc1 partials + x-half of out_fc1.
// GEMM: x (A=32 rows, K=64) x 1792 columns, one CTA per (b,t).
// ---------------------------------------------------------------------------
__global__ __launch_bounds__(256) void k_fc1(const float* __restrict__ inputs,
                                             const float* __restrict__ w1,
                                             const float* __restrict__ wo1) {
    __shared__ __align__(16) float xsT[64 * 36];   // [d][a] padded
    int bt = blockIdx.x;
    int b = bt / TT;
    int t = bt - b * TT;
    int tid = threadIdx.x;

    for (int idx = tid; idx < AA * DD; idx += 256) {
        int a = idx >> 6, d = idx & 63;
        xsT[d * 36 + a] = inputs[((b * AA + a) * TFULL + t) * DD + d];
    }
    __syncthreads();

    #pragma unroll 1
    for (int j = 0; j < 7; j++) {
        int c = tid + (j << 8);          // 0..1791
        int n = c & 255;
        const float* wcol;
        if (c < 1536) {
            int ip = c >> 9;             // type' 0..2  (actual type ip+1)
            int half = (c >> 8) & 1;     // 0 = send, 1 = rec
            wcol = w1 + ((ip + 1) * 128 + half * 64) * 256 + n;
        } else {
            wcol = wo1 + n;              // out_fc1_w rows 0..63 (x part)
        }
        uint64_t acc2[16];
        #pragma unroll
        for (int p = 0; p < 16; p++) acc2[p] = 0ull;

        #pragma unroll 4
        for (int d = 0; d < 64; d++) {
            uint64_t wp = pack_dup(wcol[d * 256]);
            const ulonglong2* row = (const ulonglong2*)(xsT + d * 36);
            #pragma unroll
            for (int h = 0; h < 8; h++) {
                ulonglong2 q = row[h];
                ffma2(acc2[2 * h + 0], q.x, wp);
                ffma2(acc2[2 * h + 1], q.y, wp);
            }
        }
        float* dst = (c < 1536) ? (g_P + (size_t)(c >> 8) * (ROWS * MH)) : g_XO1;
        #pragma unroll
        for (int p = 0; p < 16; p++) {
            dst[(size_t)(bt * 32 + 2 * p + 0) * 256 + n] = lo32(acc2[p]);
            dst[(size_t)(bt * 32 + 2 * p + 1) * 256 + n] = hi32(acc2[p]);
        }
    }
}

// ---------------------------------------------------------------------------
// Kernel 2: edge gates g[b,t,r,i] = sum_s rel_type[b,r,s,i] * state[b,send,t,s]
// ---------------------------------------------------------------------------
__global__ __launch_bounds__(256) void k_gate(const float* __restrict__ state,
                                              const float* __restrict__ rel_type) {
    int idx = blockIdx.x * 256 + threadIdx.x;
    if (idx >= BB * TT * RR) return;
    int r = idx % RR;
    int bt = idx / RR;
    int t = bt % TT;
    int b = bt / TT;
    int rec = r / 31;
    int e = r - rec * 31;
    int send = e + (e >= rec);
    const float* stp = state + ((b * AA + send) * TFULL + t) * SSZ;
    const float* rt = rel_type + (size_t)(b * RR + r) * SSZ * 4;
    float s0 = stp[0], s1 = stp[1], s2 = stp[2], s3 = stp[3];
    #pragma unroll
    for (int ip = 0; ip < 3; ip++) {
        float g = rt[0 * 4 + ip + 1] * s0 + rt[1 * 4 + ip + 1] * s1 +
                  rt[2 * 4 + ip + 1] * s2 + rt[3 * 4 + ip + 1] * s3;
        g_G[(size_t)idx * 3 + ip] = g;
    }
}

// ---------------------------------------------------------------------------
// Kernel 3 (heavy): per-(b,t,receiver) message fc2 + gated aggregation.
// One CTA per (b,t,a): 31 edges, 3 types.  fc2 = (31x256) @ (256x256).
// m1 transposed+padded in SMEM; inner loop: 1 LDG + 8 LDS.128 + 16 FFMA2.
// ---------------------------------------------------------------------------
__global__ __launch_bounds__(256) void k_msg(const float* __restrict__ w2,
                                             const float* __restrict__ b1,
                                             const float* __restrict__ b2) {
    __shared__ __align__(16) float sm1[256 * 36];   // [k][e] padded to 36
    __shared__ float gs[31 * 3];                    // [e][type']
    int blk = blockIdx.x;                           // bt*32 + a
    int a = blk & 31;
    int bt = blk >> 5;
    int tid = threadIdx.x;

    if (tid < 93) {
        int e = tid / 3;
        int ip = tid - e * 3;
        gs[tid] = g_G[(size_t)(bt * RR + a * 31 + e) * 3 + ip];
    }

    float agg = 0.f;
    for (int ip = 0; ip < 3; ip++) {
        __syncthreads();   // gs ready (ip=0) / sm1 free for reuse (ip>0)
        {
            const float* Psend = g_P + (size_t)(ip * 2) * (ROWS * MH) + (size_t)(bt * 32) * 256 + tid;
            const float* Prec  = g_P + (size_t)(ip * 2 + 1) * (ROWS * MH) + (size_t)(bt * 32 + a) * 256 + tid;
            float pr = *Prec + b1[(ip + 1) * 256 + tid];
            #pragma unroll
            for (int e = 0; e < 31; e++) {
                int send = e + (e >= a);
                sm1[tid * 36 + e] = lrelu(Psend[send * 256] + pr);
            }
            sm1[tid * 36 + 31] = 0.f;   // keep packed lane 31 clean
        }
        __syncthreads();

        uint64_t acc2[16];
        #pragma unroll
        for (int p = 0; p < 16; p++) acc2[p] = 0ull;

        const float* wc = w2 + (size_t)(ip + 1) * 65536 + tid;
        #pragma unroll 4
        for (int k = 0; k < 256; k++) {
            uint64_t wp = pack_dup(wc[k * 256]);
            const ulonglong2* row = (const ulonglong2*)(sm1 + k * 36);
            #pragma unroll
            for (int h = 0; h < 8; h++) {
                ulonglong2 q = row[h];
                ffma2(acc2[2 * h + 0], q.x, wp);
                ffma2(acc2[2 * h + 1], q.y, wp);
            }
        }
        float b2n = b2[(ip + 1) * 256 + tid];
        #pragma unroll
        for (int p = 0; p < 16; p++) {
            int e0 = 2 * p, e1 = 2 * p + 1;
            agg += lrelu(lo32(acc2[p]) + b2n) * gs[e0 * 3 + ip];
            if (e1 < 31)
                agg += lrelu(hi32(acc2[p]) + b2n) * gs[e1 * 3 + ip];
        }
    }
    g_AGG[(size_t)blk * 256 + tid] = agg;
}

// ---------------------------------------------------------------------------
// Kernel 4: output MLP, one CTA per (b,t) handling all 32 agents.
// ---------------------------------------------------------------------------
__global__ __launch_bounds__(256) void k_out(const float* __restrict__ inputs,
                                             const float* __restrict__ wo1,
                                             const float* __restrict__ bo1,
                                             const float* __restrict__ wo2,
                                             const float* __restrict__ bo2,
                                             const float* __restrict__ wo3,
                                             const float* __restrict__ bo3,
                                             float* __restrict__ out) {
    extern __shared__ float s3[];
    float* sA = s3;              // [256][36]
    float* sB = s3 + 256 * 36;   // [256][36]
    int bt = blockIdx.x;
    int b = bt / TT;
    int t = bt - b * TT;
    int tid = threadIdx.x;

    // load agg transposed: sA[k][a]
    for (int idx = tid; idx < 32 * 256; idx += 256) {
        int a = idx >> 8;
        int k = idx & 255;
        sA[k * 36 + a] = g_AGG[(size_t)(bt * 32 + a) * 256 + k];
    }
    __syncthreads();

    uint64_t acc2[16];

    // ---- h1 ----
    {
        const float* xb = g_XO1 + (size_t)(bt * 32) * 256 + tid;
        float bb = bo1[tid];
        #pragma unroll
        for (int p = 0; p < 16; p++)
            acc2[p] = pack2(xb[(2 * p + 0) * 256] + bb, xb[(2 * p + 1) * 256] + bb);
        const float* wc = wo1 + 64 * 256 + tid;
        #pragma unroll 4
        for (int k = 0; k < 256; k++) {
            uint64_t wp = pack_dup(wc[k * 256]);
            const ulonglong2* row = (const ulonglong2*)(sA + k * 36);
            #pragma unroll
            for (int h = 0; h < 8; h++) {
                ulonglong2 q = row[h];
                ffma2(acc2[2 * h + 0], q.x, wp);
                ffma2(acc2[2 * h + 1], q.y, wp);
            }
        }
        #pragma unroll
        for (int p = 0; p < 16; p++) {
            sB[tid * 36 + 2 * p + 0] = lrelu(lo32(acc2[p]));
            sB[tid * 36 + 2 * p + 1] = lrelu(hi32(acc2[p]));
        }
    }
    __syncthreads();

    // ---- h2 ----
    {
        float bb = bo2[tid];
        #pragma unroll
        for (int p = 0; p < 16; p++) acc2[p] = pack2(bb, bb);
        const float* wc = wo2 + tid;
        #pragma unroll 4
        for (int k = 0; k < 256; k++) {
            uint64_t wp = pack_dup(wc[k * 256]);
            const ulonglong2* row = (const ulonglong2*)(sB + k * 36);
            #pragma unroll
            for (int h = 0; h < 8; h++) {
                ulonglong2 q = row[h];
                ffma2(acc2[2 * h + 0], q.x, wp);
                ffma2(acc2[2 * h + 1], q.y, wp);
            }
        }
    }
    __syncthreads();              // all reads of sA done
    #pragma unroll
    for (int p = 0; p < 16; p++) {
        sA[tid * 36 + 2 * p + 0] = lrelu(lo32(acc2[p]));
        sA[tid * 36 + 2 * p + 1] = lrelu(hi32(acc2[p]));
    }
    __syncthreads();

    // ---- fc3 partials: thread (kq, d) handles 64 k's for column d ----
    {
        int d = tid & 63;
        int kq = tid >> 6;
        #pragma unroll
        for (int p = 0; p < 16; p++) acc2[p] = 0ull;
        const float* wc = wo3 + d;
        int k0 = kq * 64;
        #pragma unroll 4
        for (int k = k0; k < k0 + 64; k++) {
            uint64_t wp = pack_dup(wc[k * 64]);
            const ulonglong2* row = (const ulonglong2*)(sA + k * 36);
            #pragma unroll
            for (int h = 0; h < 8; h++) {
                ulonglong2 q = row[h];
                ffma2(acc2[2 * h + 0], q.x, wp);
                ffma2(acc2[2 * h + 1], q.y, wp);
            }
        }
        #pragma unroll
        for (int p = 0; p < 16; p++) {
            sB[tid * 36 + 2 * p + 0] = lo32(acc2[p]);
            sB[tid * 36 + 2 * p + 1] = hi32(acc2[p]);
        }
    }
    __syncthreads();

    // ---- reduce partials, add bias + residual, write transposed output ----
    for (int idx = tid; idx < 2048; idx += 256) {
        int a = idx >> 6;
        int d = idx & 63;
        float v = sB[d * 36 + a] + sB[(64 + d) * 36 + a] +
                  sB[(128 + d) * 36 + a] + sB[(192 + d) * 36 + a];
        v += bo3[d];
        v += inputs[((b * AA + a) * TFULL + t) * DD + d];
        out[((size_t)(b * AA + a) * TT + t) * DD + d] = v;
    }
}

// ---------------------------------------------------------------------------
extern "C" void kernel_launch(void* const* d_in, const int* in_sizes, int n_in,
                              void* d_out, int out_size) {
    const float* inputs    = (const float*)d_in[0];
    const float* state     = (const float*)d_in[1];
    const float* rel_type  = (const float*)d_in[2];
    // d_in[3] rel_rec, d_in[4] rel_send: implied by edge ordering, unused
    const float* msg_fc1_w = (const float*)d_in[5];
    const float* msg_fc1_b = (const float*)d_in[6];
    const float* msg_fc2_w = (const float*)d_in[7];
    const float* msg_fc2_b = (const float*)d_in[8];
    const float* out_fc1_w = (const float*)d_in[9];
    const float* out_fc1_b = (const float*)d_in[10];
    const float* out_fc2_w = (const float*)d_in[11];
    const float* out_fc2_b = (const float*)d_in[12];
    const float* out_fc3_w = (const float*)d_in[13];
    const float* out_fc3_b = (const float*)d_in[14];
    float* out = (float*)d_out;

    static_assert(BB * TT * RR == 249984, "edge count");
    cudaFuncSetAttribute(k_out, cudaFuncAttributeMaxDynamicSharedMemorySize, 2 * 256 * 36 * 4);

    k_fc1<<<BT, 256>>>(inputs, msg_fc1_w, out_fc1_w);
    k_gate<<<(BB * TT * RR + 255) / 256, 256>>>(state, rel_type);
    k_msg<<<ROWS, 256>>>(msg_fc2_w, msg_fc1_b, msg_fc2_b);
    k_out<<<BT, 256, 2 * 256 * 36 * 4>>>(inputs, out_fc1_w, out_fc1_b,
                                         out_fc2_w, out_fc2_b,
                                         out_fc3_w, out_fc3_b, out);
}